// round 3
// baseline (speedup 1.0000x reference)
#include <cuda_runtime.h>
#include <cuda_bf16.h>
#include <math.h>
#include <stdint.h>

// Problem constants
#define T_DIM 32768
#define H_DIM 1024
#define V_DIM 32
#define D_DIM 1024

// GEMM tiling
#define BM 128
#define BN 128
#define BK 32                      // bf16 K elements per chunk
#define NCHUNK (H_DIM / BK)        // 32
#define STAGES 4
#define RSTRIDE 80                 // padded smem row stride (64B data + 16B pad)
#define MAT_BYTES (128 * RSTRIDE)  // 10240
#define OFF_AH 0
#define OFF_AL (1 * MAT_BYTES)
#define OFF_BH (2 * MAT_BYTES)
#define OFF_BL (3 * MAT_BYTES)
#define STAGE_BYTES (4 * MAT_BYTES)          // 40960
#define GEMM_SMEM (STAGES * STAGE_BYTES)     // 163840

// ---------------------------------------------------------------------------
// Device scratch
// ---------------------------------------------------------------------------
__device__ int g_tok[T_DIM];
__device__ int g_run_first[T_DIM + 1];
__device__ int g_row_start[T_DIM];
__device__ int g_row_count[T_DIM];
__device__ int g_nseg;
__device__ int g_nvalid;
__device__ __align__(16) __nv_bfloat16 g_C_hi[(size_t)T_DIM * H_DIM];  // 64 MB
__device__ __align__(16) __nv_bfloat16 g_C_lo[(size_t)T_DIM * H_DIM];  // 64 MB
__device__ __align__(16) __nv_bfloat16 g_W_hi[(size_t)D_DIM * H_DIM];  // 2 MB
__device__ __align__(16) __nv_bfloat16 g_W_lo[(size_t)D_DIM * H_DIM];  // 2 MB

__device__ __forceinline__ void split_bf16(float x, __nv_bfloat16& hi, __nv_bfloat16& lo) {
    hi = __float2bfloat16(x);
    lo = __float2bfloat16(x - __bfloat162float(hi));
}

__device__ __forceinline__ uint32_t smem_to_u32(const void* p) {
    uint32_t a;
    asm("{ .reg .u64 t; cvta.to.shared.u64 t, %1; cvt.u32.u64 %0, t; }" : "=r"(a) : "l"(p));
    return a;
}

// ---------------------------------------------------------------------------
// Arch-neutral async-copy / mma helpers (sm_80+ PTX, legal on sm_100 target)
// ---------------------------------------------------------------------------
__device__ __forceinline__ void cp16(uint32_t dst, const void* src) {
    asm volatile("cp.async.cg.shared.global [%0], [%1], 16;" :: "r"(dst), "l"(src));
}
#define CP_COMMIT() asm volatile("cp.async.commit_group;" ::: "memory")
#define CP_WAIT2()  asm volatile("cp.async.wait_group 2;" ::: "memory")

__device__ __forceinline__ void ldsm4(uint32_t a, uint32_t& r0, uint32_t& r1,
                                      uint32_t& r2, uint32_t& r3) {
    asm volatile("ldmatrix.sync.aligned.m8n8.x4.shared.b16 {%0,%1,%2,%3}, [%4];"
                 : "=r"(r0), "=r"(r1), "=r"(r2), "=r"(r3) : "r"(a));
}
__device__ __forceinline__ void mma16816(float* c, const uint32_t* a, const uint32_t* b) {
    asm volatile("mma.sync.aligned.m16n8k16.row.col.f32.bf16.bf16.f32 "
                 "{%0,%1,%2,%3}, {%4,%5,%6,%7}, {%8,%9}, {%0,%1,%2,%3};"
                 : "+f"(c[0]), "+f"(c[1]), "+f"(c[2]), "+f"(c[3])
                 : "r"(a[0]), "r"(a[1]), "r"(a[2]), "r"(a[3]), "r"(b[0]), "r"(b[1]));
}

// ---------------------------------------------------------------------------
// Kernel 1: per-token argmax over V=32 logits (first-max tie rule)
// ---------------------------------------------------------------------------
__global__ __launch_bounds__(256) void argmax_kernel(const float* __restrict__ logits) {
    int t = blockIdx.x * 256 + threadIdx.x;
    if (t >= T_DIM) return;
    const float4* p = (const float4*)(logits + (size_t)t * V_DIM);
    float best = -INFINITY;
    int bi = 0;
#pragma unroll
    for (int q = 0; q < V_DIM / 4; q++) {
        float4 v = p[q];
        int b0 = q * 4;
        if (v.x > best) { best = v.x; bi = b0 + 0; }
        if (v.y > best) { best = v.y; bi = b0 + 1; }
        if (v.z > best) { best = v.z; bi = b0 + 2; }
        if (v.w > best) { best = v.w; bi = b0 + 3; }
    }
    g_tok[t] = bi;
}

// ---------------------------------------------------------------------------
// Kernel 2: segmentation (single 1024-thread block; two shared-memory scans)
// ---------------------------------------------------------------------------
__global__ __launch_bounds__(1024) void segment_kernel() {
    __shared__ int s[1024];
    __shared__ int s_total;
    const int tid  = threadIdx.x;
    const int CH   = T_DIM / 1024;   // 32
    const int base = tid * CH;

    int prev = (base == 0) ? -1 : g_tok[base - 1];
    int cnt = 0;
    unsigned flags = 0;
#pragma unroll
    for (int i = 0; i < CH; i++) {
        int cur = g_tok[base + i];
        int st = (cur != prev) ? 1 : 0;
        flags |= ((unsigned)st) << i;
        cnt += st;
        prev = cur;
    }
    s[tid] = cnt;
    __syncthreads();
    for (int off = 1; off < 1024; off <<= 1) {
        int add = (tid >= off) ? s[tid - off] : 0;
        __syncthreads();
        s[tid] += add;
        __syncthreads();
    }
    int incl = s[tid];
    int excl = incl - cnt;
    if (tid == 1023) s_total = incl;
    {
        int r = excl;
#pragma unroll
        for (int i = 0; i < CH; i++)
            if ((flags >> i) & 1u) g_run_first[r++] = base + i;
    }
    __syncthreads();
    const int n_seg = s_total;
    if (tid == 0) {
        g_run_first[n_seg] = T_DIM;
        g_nseg = n_seg;
    }
    __syncthreads();

    int vcnt = 0;
    unsigned vflags = 0;
#pragma unroll
    for (int i = 0; i < CH; i++) {
        int sidx = base + i;
        if (sidx < n_seg) {
            int f = g_run_first[sidx];
            int v = (g_tok[f] != 0) ? 1 : 0;
            vflags |= ((unsigned)v) << i;
            vcnt += v;
        }
    }
    __syncthreads();
    s[tid] = vcnt;
    __syncthreads();
    for (int off = 1; off < 1024; off <<= 1) {
        int add = (tid >= off) ? s[tid - off] : 0;
        __syncthreads();
        s[tid] += add;
        __syncthreads();
    }
    int vincl = s[tid];
    int vexcl = vincl - vcnt;
    if (tid == 1023) s_total = vincl;
    {
        int d = vexcl;
#pragma unroll
        for (int i = 0; i < CH; i++) {
            int sidx = base + i;
            if (sidx < n_seg && ((vflags >> i) & 1u)) {
                int f = g_run_first[sidx];
                g_row_start[d] = f;
                g_row_count[d] = g_run_first[sidx + 1] - f;
                d++;
            }
        }
    }
    __syncthreads();
    if (tid == 0) g_nvalid = s_total;
}

// ---------------------------------------------------------------------------
// Kernel 3: segment mean + split to bf16 hi/lo. One block per compact row.
// ---------------------------------------------------------------------------
__global__ __launch_bounds__(256) void mean_split_kernel(const float* __restrict__ hidden) {
    int r = blockIdx.x;
    if (r >= g_nvalid) return;
    int start = g_row_start[r];
    int cnt   = g_row_count[r];
    int i = threadIdx.x;
    const float4* src = (const float4*)(hidden + (size_t)start * H_DIM);
    float4 a = src[i];
    for (int j = 1; j < cnt; j++) {
        const float4* s2 = (const float4*)(hidden + (size_t)(start + j) * H_DIM);
        float4 v = s2[i];
        a.x += v.x; a.y += v.y; a.z += v.z; a.w += v.w;
    }
    if (cnt > 1) {
        float inv = 1.0f / (float)cnt;
        a.x *= inv; a.y *= inv; a.z *= inv; a.w *= inv;
    }
    __nv_bfloat16 h0, h1, h2, h3, l0, l1, l2, l3;
    split_bf16(a.x, h0, l0); split_bf16(a.y, h1, l1);
    split_bf16(a.z, h2, l2); split_bf16(a.w, h3, l3);
    ushort4 hv, lv;
    hv.x = __bfloat16_as_ushort(h0); hv.y = __bfloat16_as_ushort(h1);
    hv.z = __bfloat16_as_ushort(h2); hv.w = __bfloat16_as_ushort(h3);
    lv.x = __bfloat16_as_ushort(l0); lv.y = __bfloat16_as_ushort(l1);
    lv.z = __bfloat16_as_ushort(l2); lv.w = __bfloat16_as_ushort(l3);
    size_t idx = (size_t)r * (H_DIM / 4) + i;
    ((ushort4*)g_C_hi)[idx] = hv;
    ((ushort4*)g_C_lo)[idx] = lv;
}

// ---------------------------------------------------------------------------
// Kernel 4: W -> hi/lo bf16
// ---------------------------------------------------------------------------
__global__ __launch_bounds__(256) void w_split_kernel(const float* __restrict__ W) {
    size_t i = (size_t)blockIdx.x * 256 + threadIdx.x;
    float4 a = ((const float4*)W)[i];
    __nv_bfloat16 h0, h1, h2, h3, l0, l1, l2, l3;
    split_bf16(a.x, h0, l0); split_bf16(a.y, h1, l1);
    split_bf16(a.z, h2, l2); split_bf16(a.w, h3, l3);
    ushort4 hv, lv;
    hv.x = __bfloat16_as_ushort(h0); hv.y = __bfloat16_as_ushort(h1);
    hv.z = __bfloat16_as_ushort(h2); hv.w = __bfloat16_as_ushort(h3);
    lv.x = __bfloat16_as_ushort(l0); lv.y = __bfloat16_as_ushort(l1);
    lv.z = __bfloat16_as_ushort(l2); lv.w = __bfloat16_as_ushort(l3);
    ((ushort4*)g_W_hi)[i] = hv;
    ((ushort4*)g_W_lo)[i] = lv;
}

// ---------------------------------------------------------------------------
// Kernel 5: split-bf16 GEMM via mma.sync.m16n8k16.
// 128x128x32 CTA tile, 8 warps (2x4), 64x32 warp tile, 4-stage cp.async.
// ---------------------------------------------------------------------------
__device__ __forceinline__ void fill_stage(uint32_t sb, int m0, int n0, int chunk, int tid) {
    const int k0 = chunk * BK;
#pragma unroll
    for (int h = 0; h < 2; h++) {
        int s2 = tid + h * 256;
        int row = s2 >> 2, seg = s2 & 3;
        uint32_t d = sb + row * RSTRIDE + seg * 16;
        size_t ga = (size_t)(m0 + row) * H_DIM + k0 + seg * 8;
        size_t gb = (size_t)(n0 + row) * H_DIM + k0 + seg * 8;
        cp16(d + OFF_AH, g_C_hi + ga);
        cp16(d + OFF_AL, g_C_lo + ga);
        cp16(d + OFF_BH, g_W_hi + gb);
        cp16(d + OFF_BL, g_W_lo + gb);
    }
}

__global__ __launch_bounds__(256, 1) void gemm_mma_kernel(const float* __restrict__ bias,
                                                          float* __restrict__ out) {
    extern __shared__ char smem[];
    const int n_valid = g_nvalid;
    const int m0 = blockIdx.y * BM;
    const int n0 = blockIdx.x * BN;
    const int tid = threadIdx.x;

    if (m0 >= n_valid) {      // fully masked: zeros
        float4 z = make_float4(0.f, 0.f, 0.f, 0.f);
        for (int i = tid; i < BM * (BN / 4); i += 256) {
            int r = i >> 5, c4 = i & 31;
            ((float4*)(out + (size_t)(m0 + r) * D_DIM + n0))[c4] = z;
        }
        return;
    }

    const int wid = tid >> 5, lane = tid & 31;
    const int warp_m = wid >> 2;   // 0..1
    const int warp_n = wid & 3;    // 0..3
    uint32_t sb = smem_to_u32(smem);

    // ldmatrix per-lane base offsets (row stride 80B -> conflict-free)
    const uint32_t a_lane = (uint32_t)((warp_m * 64 + (lane & 15)) * RSTRIDE + (lane >> 4) * 16);
    const uint32_t b_lane = (uint32_t)((warp_n * 32 + (lane & 15)) * RSTRIDE + (lane >> 4) * 16);

    float acc[4][4][4];
#pragma unroll
    for (int i = 0; i < 4; i++)
#pragma unroll
        for (int j = 0; j < 4; j++)
#pragma unroll
            for (int k = 0; k < 4; k++) acc[i][j][k] = 0.f;

    fill_stage(sb + 0 * STAGE_BYTES, m0, n0, 0, tid); CP_COMMIT();
    fill_stage(sb + 1 * STAGE_BYTES, m0, n0, 1, tid); CP_COMMIT();
    fill_stage(sb + 2 * STAGE_BYTES, m0, n0, 2, tid); CP_COMMIT();

    for (int c = 0; c < NCHUNK; c++) {
        CP_WAIT2();
        __syncthreads();
        // refill oldest stage (consumed at iteration c-1; sync above covers it)
        if (c + 3 < NCHUNK) fill_stage(sb + ((c + 3) & 3) * STAGE_BYTES, m0, n0, c + 3, tid);
        CP_COMMIT();   // empty groups at tail keep wait_group bookkeeping exact

        const uint32_t st = sb + (c & 3) * STAGE_BYTES;
#pragma unroll
        for (int ks = 0; ks < 2; ks++) {
            uint32_t ah[4][4], al[4][4], bh[4][2], bl[4][2];
#pragma unroll
            for (int mi = 0; mi < 4; mi++) {
                uint32_t ad = st + OFF_AH + a_lane + mi * (16 * RSTRIDE) + ks * 32;
                ldsm4(ad, ah[mi][0], ah[mi][1], ah[mi][2], ah[mi][3]);
                ldsm4(ad + (OFF_AL - OFF_AH), al[mi][0], al[mi][1], al[mi][2], al[mi][3]);
            }
#pragma unroll
            for (int j = 0; j < 2; j++) {
                uint32_t bd = st + OFF_BH + b_lane + j * (16 * RSTRIDE) + ks * 32;
                uint32_t r0, r1, r2, r3;
                ldsm4(bd, r0, r1, r2, r3);
                bh[2 * j][0] = r0; bh[2 * j + 1][0] = r1;
                bh[2 * j][1] = r2; bh[2 * j + 1][1] = r3;
                ldsm4(bd + (OFF_BL - OFF_BH), r0, r1, r2, r3);
                bl[2 * j][0] = r0; bl[2 * j + 1][0] = r1;
                bl[2 * j][1] = r2; bl[2 * j + 1][1] = r3;
            }
#pragma unroll
            for (int mi = 0; mi < 4; mi++)
#pragma unroll
                for (int ni = 0; ni < 4; ni++) {
                    mma16816(acc[mi][ni], ah[mi], bh[ni]);   // hi*hi
                    mma16816(acc[mi][ni], ah[mi], bl[ni]);   // hi*lo
                    mma16816(acc[mi][ni], al[mi], bh[ni]);   // lo*hi
                }
        }
    }

    // Epilogue: bias + row mask, direct float2 stores
    const int r_in = lane >> 2;
    const int c2 = (lane & 3) * 2;
#pragma unroll
    for (int mi = 0; mi < 4; mi++) {
#pragma unroll
        for (int half = 0; half < 2; half++) {
            int row = m0 + warp_m * 64 + mi * 16 + r_in + half * 8;
            bool rv = row < n_valid;
            float* op = out + (size_t)row * D_DIM;
#pragma unroll
            for (int ni = 0; ni < 4; ni++) {
                int col = n0 + warp_n * 32 + ni * 8 + c2;
                float2 v;
                if (rv) {
                    v.x = acc[mi][ni][half * 2 + 0] + __ldg(bias + col);
                    v.y = acc[mi][ni][half * 2 + 1] + __ldg(bias + col + 1);
                } else {
                    v.x = 0.f; v.y = 0.f;
                }
                *(float2*)(op + col) = v;
            }
        }
    }
}

// ---------------------------------------------------------------------------
// Launch
// ---------------------------------------------------------------------------
extern "C" void kernel_launch(void* const* d_in, const int* in_sizes, int n_in,
                              void* d_out, int out_size) {
    const float* hidden = (const float*)d_in[0];   // [1, T, H]
    const float* logits = (const float*)d_in[1];   // [1, T, V]
    const float* W      = (const float*)d_in[2];   // [D, H]
    const float* bias   = (const float*)d_in[3];   // [D]
    float* out          = (float*)d_out;           // [1, T, D]

    cudaFuncSetAttribute(gemm_mma_kernel, cudaFuncAttributeMaxDynamicSharedMemorySize,
                         GEMM_SMEM);

    w_split_kernel<<<(D_DIM * H_DIM) / (256 * 4), 256>>>(W);
    argmax_kernel<<<T_DIM / 256, 256>>>(logits);
    segment_kernel<<<1, 1024>>>();
    mean_split_kernel<<<T_DIM, 256>>>(hidden);
    dim3 grid(D_DIM / BN, T_DIM / BM);
    gemm_mma_kernel<<<grid, 256, GEMM_SMEM>>>(bias, out);
}

// round 4
// speedup vs baseline: 2.1502x; 2.1502x over previous
#include <cuda_runtime.h>
#include <cuda_fp16.h>
#include <math.h>
#include <stdint.h>

// Problem constants
#define T_DIM 32768
#define H_DIM 1024
#define V_DIM 32
#define D_DIM 1024

// GEMM tiling
#define BM 128
#define BN 128
#define BK 32                      // fp16 K elements per chunk (64 B/row)
#define NCHUNK (H_DIM / BK)        // 32
#define RSTRIDE 80                 // padded smem row stride
#define MAT_BYTES (128 * RSTRIDE)  // 10240
#define OFF_A 0
#define OFF_B MAT_BYTES
#define STAGE_BYTES (2 * MAT_BYTES)          // 20480
#define GEMM_SMEM (4 * STAGE_BYTES)          // 81920

// ---------------------------------------------------------------------------
// Device scratch
// ---------------------------------------------------------------------------
__device__ int g_tok[T_DIM];
__device__ int g_run_first[T_DIM + 1];
__device__ int g_row_start[T_DIM];
__device__ int g_row_count[T_DIM];
__device__ int g_nseg;
__device__ int g_nvalid;
__device__ __align__(16) __half g_C_h[(size_t)T_DIM * H_DIM];  // 64 MB
__device__ __align__(16) __half g_W_h[(size_t)D_DIM * H_DIM];  // 2 MB

__device__ __forceinline__ uint32_t smem_to_u32(const void* p) {
    uint32_t a;
    asm("{ .reg .u64 t; cvta.to.shared.u64 t, %1; cvt.u32.u64 %0, t; }" : "=r"(a) : "l"(p));
    return a;
}

// ---------------------------------------------------------------------------
// Arch-neutral async-copy / mma helpers (sm_80+ PTX, legal on sm_100 target)
// ---------------------------------------------------------------------------
__device__ __forceinline__ void cp16(uint32_t dst, const void* src) {
    asm volatile("cp.async.cg.shared.global [%0], [%1], 16;" :: "r"(dst), "l"(src));
}
#define CP_COMMIT() asm volatile("cp.async.commit_group;" ::: "memory")
#define CP_WAIT2()  asm volatile("cp.async.wait_group 2;" ::: "memory")

__device__ __forceinline__ void ldsm4(uint32_t a, uint32_t& r0, uint32_t& r1,
                                      uint32_t& r2, uint32_t& r3) {
    asm volatile("ldmatrix.sync.aligned.m8n8.x4.shared.b16 {%0,%1,%2,%3}, [%4];"
                 : "=r"(r0), "=r"(r1), "=r"(r2), "=r"(r3) : "r"(a));
}
__device__ __forceinline__ void mma16816(float* c, const uint32_t* a, const uint32_t* b) {
    asm volatile("mma.sync.aligned.m16n8k16.row.col.f32.f16.f16.f32 "
                 "{%0,%1,%2,%3}, {%4,%5,%6,%7}, {%8,%9}, {%0,%1,%2,%3};"
                 : "+f"(c[0]), "+f"(c[1]), "+f"(c[2]), "+f"(c[3])
                 : "r"(a[0]), "r"(a[1]), "r"(a[2]), "r"(a[3]), "r"(b[0]), "r"(b[1]));
}

// ---------------------------------------------------------------------------
// Kernel 1: per-token argmax over V=32 logits (first-max tie rule)
// ---------------------------------------------------------------------------
__global__ __launch_bounds__(256) void argmax_kernel(const float* __restrict__ logits) {
    int t = blockIdx.x * 256 + threadIdx.x;
    if (t >= T_DIM) return;
    const float4* p = (const float4*)(logits + (size_t)t * V_DIM);
    float best = -INFINITY;
    int bi = 0;
#pragma unroll
    for (int q = 0; q < V_DIM / 4; q++) {
        float4 v = p[q];
        int b0 = q * 4;
        if (v.x > best) { best = v.x; bi = b0 + 0; }
        if (v.y > best) { best = v.y; bi = b0 + 1; }
        if (v.z > best) { best = v.z; bi = b0 + 2; }
        if (v.w > best) { best = v.w; bi = b0 + 3; }
    }
    g_tok[t] = bi;
}

// ---------------------------------------------------------------------------
// Kernel 2: segmentation (single 1024-thread block; two shared-memory scans)
// ---------------------------------------------------------------------------
__global__ __launch_bounds__(1024) void segment_kernel() {
    __shared__ int s[1024];
    __shared__ int s_total;
    const int tid  = threadIdx.x;
    const int CH   = T_DIM / 1024;   // 32
    const int base = tid * CH;

    int prev = (base == 0) ? -1 : g_tok[base - 1];
    int cnt = 0;
    unsigned flags = 0;
#pragma unroll
    for (int i = 0; i < CH; i++) {
        int cur = g_tok[base + i];
        int st = (cur != prev) ? 1 : 0;
        flags |= ((unsigned)st) << i;
        cnt += st;
        prev = cur;
    }
    s[tid] = cnt;
    __syncthreads();
    for (int off = 1; off < 1024; off <<= 1) {
        int add = (tid >= off) ? s[tid - off] : 0;
        __syncthreads();
        s[tid] += add;
        __syncthreads();
    }
    int incl = s[tid];
    int excl = incl - cnt;
    if (tid == 1023) s_total = incl;
    {
        int r = excl;
#pragma unroll
        for (int i = 0; i < CH; i++)
            if ((flags >> i) & 1u) g_run_first[r++] = base + i;
    }
    __syncthreads();
    const int n_seg = s_total;
    if (tid == 0) {
        g_run_first[n_seg] = T_DIM;
        g_nseg = n_seg;
    }
    __syncthreads();

    int vcnt = 0;
    unsigned vflags = 0;
#pragma unroll
    for (int i = 0; i < CH; i++) {
        int sidx = base + i;
        if (sidx < n_seg) {
            int f = g_run_first[sidx];
            int v = (g_tok[f] != 0) ? 1 : 0;
            vflags |= ((unsigned)v) << i;
            vcnt += v;
        }
    }
    __syncthreads();
    s[tid] = vcnt;
    __syncthreads();
    for (int off = 1; off < 1024; off <<= 1) {
        int add = (tid >= off) ? s[tid - off] : 0;
        __syncthreads();
        s[tid] += add;
        __syncthreads();
    }
    int vincl = s[tid];
    int vexcl = vincl - vcnt;
    if (tid == 1023) s_total = vincl;
    {
        int d = vexcl;
#pragma unroll
        for (int i = 0; i < CH; i++) {
            int sidx = base + i;
            if (sidx < n_seg && ((vflags >> i) & 1u)) {
                int f = g_run_first[sidx];
                g_row_start[d] = f;
                g_row_count[d] = g_run_first[sidx + 1] - f;
                d++;
            }
        }
    }
    __syncthreads();
    if (tid == 0) g_nvalid = s_total;
}

// ---------------------------------------------------------------------------
// Kernel 3: segment mean -> fp16. One block per compact row.
// ---------------------------------------------------------------------------
__global__ __launch_bounds__(256) void mean_kernel(const float* __restrict__ hidden) {
    int r = blockIdx.x;
    if (r >= g_nvalid) return;
    int start = g_row_start[r];
    int cnt   = g_row_count[r];
    int i = threadIdx.x;
    const float4* src = (const float4*)(hidden + (size_t)start * H_DIM);
    float4 a = src[i];
    for (int j = 1; j < cnt; j++) {
        const float4* s2 = (const float4*)(hidden + (size_t)(start + j) * H_DIM);
        float4 v = s2[i];
        a.x += v.x; a.y += v.y; a.z += v.z; a.w += v.w;
    }
    if (cnt > 1) {
        float inv = 1.0f / (float)cnt;
        a.x *= inv; a.y *= inv; a.z *= inv; a.w *= inv;
    }
    __half2 p0 = __floats2half2_rn(a.x, a.y);
    __half2 p1 = __floats2half2_rn(a.z, a.w);
    uint2 u;
    u.x = *(const uint32_t*)&p0;
    u.y = *(const uint32_t*)&p1;
    ((uint2*)g_C_h)[(size_t)r * (H_DIM / 4) + i] = u;
}

// ---------------------------------------------------------------------------
// Kernel 4: W -> fp16
// ---------------------------------------------------------------------------
__global__ __launch_bounds__(256) void w_half_kernel(const float* __restrict__ W) {
    size_t i = (size_t)blockIdx.x * 256 + threadIdx.x;
    float4 a = ((const float4*)W)[i];
    __half2 p0 = __floats2half2_rn(a.x, a.y);
    __half2 p1 = __floats2half2_rn(a.z, a.w);
    uint2 u;
    u.x = *(const uint32_t*)&p0;
    u.y = *(const uint32_t*)&p1;
    ((uint2*)g_W_h)[i] = u;
}

// ---------------------------------------------------------------------------
// Kernel 5: single-pass fp16 GEMM via mma.sync.m16n8k16.
// 128x128x32 CTA tile, 8 warps (2x4), 64x32 warp tile, 4-stage cp.async.
// ---------------------------------------------------------------------------
__device__ __forceinline__ void fill_stage(uint32_t sb, int m0, int n0, int chunk, int tid) {
    const int k0 = chunk * BK;
#pragma unroll
    for (int h = 0; h < 2; h++) {
        int s2 = tid + h * 256;
        int row = s2 >> 2, seg = s2 & 3;
        uint32_t d = sb + row * RSTRIDE + seg * 16;
        cp16(d + OFF_A, g_C_h + (size_t)(m0 + row) * H_DIM + k0 + seg * 8);
        cp16(d + OFF_B, g_W_h + (size_t)(n0 + row) * H_DIM + k0 + seg * 8);
    }
}

__global__ __launch_bounds__(256, 2) void gemm_mma_kernel(const float* __restrict__ bias,
                                                          float* __restrict__ out) {
    extern __shared__ char smem[];
    const int n_valid = g_nvalid;
    const int m0 = blockIdx.y * BM;
    const int n0 = blockIdx.x * BN;
    const int tid = threadIdx.x;

    if (m0 >= n_valid) {      // fully masked: zeros
        float4 z = make_float4(0.f, 0.f, 0.f, 0.f);
        for (int i = tid; i < BM * (BN / 4); i += 256) {
            int r = i >> 5, c4 = i & 31;
            ((float4*)(out + (size_t)(m0 + r) * D_DIM + n0))[c4] = z;
        }
        return;
    }

    const int wid = tid >> 5, lane = tid & 31;
    const int warp_m = wid >> 2;   // 0..1
    const int warp_n = wid & 3;    // 0..3
    uint32_t sb = smem_to_u32(smem);

    const uint32_t a_lane = (uint32_t)((warp_m * 64 + (lane & 15)) * RSTRIDE + (lane >> 4) * 16);
    const uint32_t b_lane = (uint32_t)((warp_n * 32 + (lane & 15)) * RSTRIDE + (lane >> 4) * 16);

    float acc[4][4][4];
#pragma unroll
    for (int i = 0; i < 4; i++)
#pragma unroll
        for (int j = 0; j < 4; j++)
#pragma unroll
            for (int k = 0; k < 4; k++) acc[i][j][k] = 0.f;

    fill_stage(sb + 0 * STAGE_BYTES, m0, n0, 0, tid); CP_COMMIT();
    fill_stage(sb + 1 * STAGE_BYTES, m0, n0, 1, tid); CP_COMMIT();
    fill_stage(sb + 2 * STAGE_BYTES, m0, n0, 2, tid); CP_COMMIT();

    for (int c = 0; c < NCHUNK; c++) {
        CP_WAIT2();
        __syncthreads();
        if (c + 3 < NCHUNK) fill_stage(sb + ((c + 3) & 3) * STAGE_BYTES, m0, n0, c + 3, tid);
        CP_COMMIT();

        const uint32_t st = sb + (c & 3) * STAGE_BYTES;
#pragma unroll
        for (int ks = 0; ks < 2; ks++) {
            uint32_t ah[4][4], bh[4][2];
#pragma unroll
            for (int mi = 0; mi < 4; mi++) {
                uint32_t ad = st + OFF_A + a_lane + mi * (16 * RSTRIDE) + ks * 32;
                ldsm4(ad, ah[mi][0], ah[mi][1], ah[mi][2], ah[mi][3]);
            }
#pragma unroll
            for (int j = 0; j < 2; j++) {
                uint32_t bd = st + OFF_B + b_lane + j * (16 * RSTRIDE) + ks * 32;
                uint32_t r0, r1, r2, r3;
                ldsm4(bd, r0, r1, r2, r3);
                bh[2 * j][0] = r0; bh[2 * j + 1][0] = r1;
                bh[2 * j][1] = r2; bh[2 * j + 1][1] = r3;
            }
#pragma unroll
            for (int mi = 0; mi < 4; mi++)
#pragma unroll
                for (int ni = 0; ni < 4; ni++)
                    mma16816(acc[mi][ni], ah[mi], bh[ni]);
        }
    }

    // Epilogue: bias + row mask
    const int r_in = lane >> 2;
    const int c2 = (lane & 3) * 2;
#pragma unroll
    for (int mi = 0; mi < 4; mi++) {
#pragma unroll
        for (int half = 0; half < 2; half++) {
            int row = m0 + warp_m * 64 + mi * 16 + r_in + half * 8;
            bool rv = row < n_valid;
            float* op = out + (size_t)row * D_DIM;
#pragma unroll
            for (int ni = 0; ni < 4; ni++) {
                int col = n0 + warp_n * 32 + ni * 8 + c2;
                float2 v;
                if (rv) {
                    v.x = acc[mi][ni][half * 2 + 0] + __ldg(bias + col);
                    v.y = acc[mi][ni][half * 2 + 1] + __ldg(bias + col + 1);
                } else {
                    v.x = 0.f; v.y = 0.f;
                }
                *(float2*)(op + col) = v;
            }
        }
    }
}

// ---------------------------------------------------------------------------
// Launch
// ---------------------------------------------------------------------------
extern "C" void kernel_launch(void* const* d_in, const int* in_sizes, int n_in,
                              void* d_out, int out_size) {
    const float* hidden = (const float*)d_in[0];   // [1, T, H]
    const float* logits = (const float*)d_in[1];   // [1, T, V]
    const float* W      = (const float*)d_in[2];   // [D, H]
    const float* bias   = (const float*)d_in[3];   // [D]
    float* out          = (float*)d_out;           // [1, T, D]

    cudaFuncSetAttribute(gemm_mma_kernel, cudaFuncAttributeMaxDynamicSharedMemorySize,
                         GEMM_SMEM);

    w_half_kernel<<<(D_DIM * H_DIM) / (256 * 4), 256>>>(W);
    argmax_kernel<<<T_DIM / 256, 256>>>(logits);
    segment_kernel<<<1, 1024>>>();
    mean_kernel<<<T_DIM, 256>>>(hidden);
    dim3 grid(D_DIM / BN, T_DIM / BM);
    gemm_mma_kernel<<<grid, 256, GEMM_SMEM>>>(bias, out);
}